// round 2
// baseline (speedup 1.0000x reference)
#include <cuda_runtime.h>

// ShortConv: fused RMSNorm (over D) -> depthwise causal conv1d (K=4, over L) -> SiLU
// Shapes: x (B=4, L=4096, D=2048) fp32; norm_weight (D); conv_weight (K,1,D).
// R2: row-pair processing, one barrier per 2 rows, all-thread smem partial sum
//     (no second barrier; double-buffered partials), 2-deep load prefetch.

#define B_ 4
#define L_ 4096
#define D_ 2048
#define K_ 4

constexpr float EPS_ = 1e-5f;
constexpr int THREADS = 512;        // 512 * 4 = D
constexpr int ROWS = 32;            // L-rows per CTA (even)
constexpr int CPB = L_ / ROWS;      // CTAs per batch = 128
constexpr int NWARPS = THREADS / 32; // 16

__device__ __forceinline__ float4 f4_scale(float4 a, float s) {
    return make_float4(a.x * s, a.y * s, a.z * s, a.w * s);
}
__device__ __forceinline__ float f4_dot(float4 a) {
    return a.x * a.x + a.y * a.y + a.z * a.z + a.w * a.w;
}

__global__ __launch_bounds__(THREADS, 2)
void shortconv_kernel(const float* __restrict__ x,
                      const float* __restrict__ norm_w,
                      const float* __restrict__ conv_w,
                      float* __restrict__ out)
{
    const int b  = blockIdx.x / CPB;
    const int l0 = (blockIdx.x % CPB) * ROWS;
    const int t  = threadIdx.x;
    const int d  = t << 2;
    const int wid = t >> 5;
    const int lane = t & 31;

    // Double-buffered warp partials: [buf][row-in-pair][warp]
    __shared__ float s_part[2][2][NWARPS];

    // Fold norm_weight into conv taps.
    const float4 g  = *reinterpret_cast<const float4*>(norm_w + d);
    float4 w0 = *reinterpret_cast<const float4*>(conv_w + 0 * D_ + d);
    float4 w1 = *reinterpret_cast<const float4*>(conv_w + 1 * D_ + d);
    float4 w2 = *reinterpret_cast<const float4*>(conv_w + 2 * D_ + d);
    float4 w3 = *reinterpret_cast<const float4*>(conv_w + 3 * D_ + d);
    w0.x *= g.x; w0.y *= g.y; w0.z *= g.z; w0.w *= g.w;
    w1.x *= g.x; w1.y *= g.y; w1.z *= g.z; w1.w *= g.w;
    w2.x *= g.x; w2.y *= g.y; w2.z *= g.z; w2.w *= g.w;
    w3.x *= g.x; w3.y *= g.y; w3.z *= g.z; w3.w *= g.w;

    const float* xb = x   + (size_t)b * L_ * D_;
    float*       ob = out + (size_t)b * L_ * D_;

    // Rolling window of normalized rows: h0 = xn[l-3], h1 = xn[l-2], h2 = xn[l-1].
    float4 h0 = make_float4(0.f, 0.f, 0.f, 0.f);
    float4 h1 = h0, h2 = h0;

    // Warmup halo of 4 rows (pair-aligned) unless at batch start.
    const int warm = (l0 == 0) ? 0 : 4;
    const int rbeg = l0 - warm;
    const int rend = l0 + ROWS;

    float4 xc0 = *reinterpret_cast<const float4*>(xb + (size_t)(rbeg + 0) * D_ + d);
    float4 xc1 = *reinterpret_cast<const float4*>(xb + (size_t)(rbeg + 1) * D_ + d);

    int buf = 0;
    for (int r = rbeg; r < rend; r += 2, buf ^= 1) {
        // Prefetch next pair before touching this pair's reduction.
        float4 xp0 = make_float4(0.f, 0.f, 0.f, 0.f);
        float4 xp1 = xp0;
        if (r + 2 < rend) {
            xp0 = *reinterpret_cast<const float4*>(xb + (size_t)(r + 2) * D_ + d);
            xp1 = *reinterpret_cast<const float4*>(xb + (size_t)(r + 3) * D_ + d);
        }

        // ---- interleaved warp reductions for both rows ----
        float s0 = f4_dot(xc0);
        float s1 = f4_dot(xc1);
        #pragma unroll
        for (int o = 16; o; o >>= 1) {
            s0 += __shfl_xor_sync(0xffffffffu, s0, o);
            s1 += __shfl_xor_sync(0xffffffffu, s1, o);
        }
        if (lane == 0) {
            s_part[buf][0][wid] = s0;
            s_part[buf][1][wid] = s1;
        }
        __syncthreads();

        // Every thread sums the 16 partials itself (broadcast LDS.128 x4 per row).
        const float4* p0 = reinterpret_cast<const float4*>(s_part[buf][0]);
        const float4* p1 = reinterpret_cast<const float4*>(s_part[buf][1]);
        float sum0 = 0.f, sum1 = 0.f;
        #pragma unroll
        for (int i = 0; i < NWARPS / 4; ++i) {
            float4 a = p0[i];
            float4 c = p1[i];
            sum0 += (a.x + a.y) + (a.z + a.w);
            sum1 += (c.x + c.y) + (c.z + c.w);
        }
        const float rinv0 = rsqrtf(sum0 * (1.0f / D_) + EPS_);
        const float rinv1 = rsqrtf(sum1 * (1.0f / D_) + EPS_);

        const float4 xn0 = f4_scale(xc0, rinv0);
        const float4 xn1 = f4_scale(xc1, rinv1);

        if (r >= l0) {
            float4 y0, y1;
            y0.x = w0.x * h0.x + w1.x * h1.x + w2.x * h2.x + w3.x * xn0.x;
            y0.y = w0.y * h0.y + w1.y * h1.y + w2.y * h2.y + w3.y * xn0.y;
            y0.z = w0.z * h0.z + w1.z * h1.z + w2.z * h2.z + w3.z * xn0.z;
            y0.w = w0.w * h0.w + w1.w * h1.w + w2.w * h2.w + w3.w * xn0.w;

            y1.x = w0.x * h1.x + w1.x * h2.x + w2.x * xn0.x + w3.x * xn1.x;
            y1.y = w0.y * h1.y + w1.y * h2.y + w2.y * xn0.y + w3.y * xn1.y;
            y1.z = w0.z * h1.z + w1.z * h2.z + w2.z * xn0.z + w3.z * xn1.z;
            y1.w = w0.w * h1.w + w1.w * h2.w + w2.w * xn0.w + w3.w * xn1.w;

            y0.x = y0.x / (1.0f + __expf(-y0.x));
            y0.y = y0.y / (1.0f + __expf(-y0.y));
            y0.z = y0.z / (1.0f + __expf(-y0.z));
            y0.w = y0.w / (1.0f + __expf(-y0.w));
            y1.x = y1.x / (1.0f + __expf(-y1.x));
            y1.y = y1.y / (1.0f + __expf(-y1.y));
            y1.z = y1.z / (1.0f + __expf(-y1.z));
            y1.w = y1.w / (1.0f + __expf(-y1.w));

            *reinterpret_cast<float4*>(ob + (size_t)(r + 0) * D_ + d) = y0;
            *reinterpret_cast<float4*>(ob + (size_t)(r + 1) * D_ + d) = y1;
        }

        // Shift window by 2 rows.
        h0 = h2; h1 = xn0; h2 = xn1;
        xc0 = xp0; xc1 = xp1;
    }
}

extern "C" void kernel_launch(void* const* d_in, const int* in_sizes, int n_in,
                              void* d_out, int out_size)
{
    const float* x  = nullptr;
    const float* nw = nullptr;
    const float* cw = nullptr;
    for (int i = 0; i < n_in; ++i) {
        if      (in_sizes[i] == B_ * L_ * D_) x  = (const float*)d_in[i];
        else if (in_sizes[i] == D_)           nw = (const float*)d_in[i];
        else if (in_sizes[i] == K_ * D_)      cw = (const float*)d_in[i];
    }
    shortconv_kernel<<<B_ * CPB, THREADS>>>(x, nw, cw, (float*)d_out);
}

// round 5
// speedup vs baseline: 1.2420x; 1.2420x over previous
#include <cuda_runtime.h>

// ShortConv: fused RMSNorm (over D) -> depthwise causal conv1d (K=4, over L) -> SiLU
// R3 (3rd submit; prior two rounds were container-acquisition infra failures):
//     SiLU via hardware tanh (MUFU.TANH) instead of IEEE division + expf.
//     sigmoid(y) = 0.5*tanh(0.5*y) + 0.5 -> 4 instr/elem, off the fma pipe.
//     Structure otherwise identical to R2 (row pairs, 1 barrier / 2 rows).

#define B_ 4
#define L_ 4096
#define D_ 2048
#define K_ 4

constexpr float EPS_ = 1e-5f;
constexpr int THREADS = 512;        // 512 * 4 = D
constexpr int ROWS = 32;            // L-rows per CTA (even)
constexpr int CPB = L_ / ROWS;      // CTAs per batch = 128
constexpr int NWARPS = THREADS / 32; // 16

__device__ __forceinline__ float4 f4_scale(float4 a, float s) {
    return make_float4(a.x * s, a.y * s, a.z * s, a.w * s);
}
__device__ __forceinline__ float f4_dot(float4 a) {
    return a.x * a.x + a.y * a.y + a.z * a.z + a.w * a.w;
}
__device__ __forceinline__ float silu_fast(float y) {
    // sigmoid(y) = 0.5*tanh(0.5*y) + 0.5 ; tanh.approx.f32 is 1 MUFU op on sm_75+
    float t;
    asm("tanh.approx.f32 %0, %1;" : "=f"(t) : "f"(0.5f * y));
    return y * fmaf(0.5f, t, 0.5f);
}

__global__ __launch_bounds__(THREADS, 2)
void shortconv_kernel(const float* __restrict__ x,
                      const float* __restrict__ norm_w,
                      const float* __restrict__ conv_w,
                      float* __restrict__ out)
{
    const int b  = blockIdx.x / CPB;
    const int l0 = (blockIdx.x % CPB) * ROWS;
    const int t  = threadIdx.x;
    const int d  = t << 2;
    const int wid = t >> 5;
    const int lane = t & 31;

    // Double-buffered warp partials: [buf][row-in-pair][warp]
    __shared__ float s_part[2][2][NWARPS];

    // Fold norm_weight into conv taps.
    const float4 g  = *reinterpret_cast<const float4*>(norm_w + d);
    float4 w0 = *reinterpret_cast<const float4*>(conv_w + 0 * D_ + d);
    float4 w1 = *reinterpret_cast<const float4*>(conv_w + 1 * D_ + d);
    float4 w2 = *reinterpret_cast<const float4*>(conv_w + 2 * D_ + d);
    float4 w3 = *reinterpret_cast<const float4*>(conv_w + 3 * D_ + d);
    w0.x *= g.x; w0.y *= g.y; w0.z *= g.z; w0.w *= g.w;
    w1.x *= g.x; w1.y *= g.y; w1.z *= g.z; w1.w *= g.w;
    w2.x *= g.x; w2.y *= g.y; w2.z *= g.z; w2.w *= g.w;
    w3.x *= g.x; w3.y *= g.y; w3.z *= g.z; w3.w *= g.w;

    const float* xb = x   + (size_t)b * L_ * D_;
    float*       ob = out + (size_t)b * L_ * D_;

    // Rolling window of normalized rows: h0 = xn[l-3], h1 = xn[l-2], h2 = xn[l-1].
    float4 h0 = make_float4(0.f, 0.f, 0.f, 0.f);
    float4 h1 = h0, h2 = h0;

    // Warmup halo of 4 rows (pair-aligned) unless at batch start.
    const int warm = (l0 == 0) ? 0 : 4;
    const int rbeg = l0 - warm;
    const int rend = l0 + ROWS;

    float4 xc0 = *reinterpret_cast<const float4*>(xb + (size_t)(rbeg + 0) * D_ + d);
    float4 xc1 = *reinterpret_cast<const float4*>(xb + (size_t)(rbeg + 1) * D_ + d);

    int buf = 0;
    for (int r = rbeg; r < rend; r += 2, buf ^= 1) {
        // Prefetch next pair before touching this pair's reduction.
        float4 xp0 = make_float4(0.f, 0.f, 0.f, 0.f);
        float4 xp1 = xp0;
        if (r + 2 < rend) {
            xp0 = *reinterpret_cast<const float4*>(xb + (size_t)(r + 2) * D_ + d);
            xp1 = *reinterpret_cast<const float4*>(xb + (size_t)(r + 3) * D_ + d);
        }

        // ---- interleaved warp reductions for both rows ----
        float s0 = f4_dot(xc0);
        float s1 = f4_dot(xc1);
        #pragma unroll
        for (int o = 16; o; o >>= 1) {
            s0 += __shfl_xor_sync(0xffffffffu, s0, o);
            s1 += __shfl_xor_sync(0xffffffffu, s1, o);
        }
        if (lane == 0) {
            s_part[buf][0][wid] = s0;
            s_part[buf][1][wid] = s1;
        }
        __syncthreads();

        // Every thread sums the 16 partials itself (broadcast LDS.128, no 2nd barrier).
        const float4* p0 = reinterpret_cast<const float4*>(s_part[buf][0]);
        const float4* p1 = reinterpret_cast<const float4*>(s_part[buf][1]);
        float sum0 = 0.f, sum1 = 0.f;
        #pragma unroll
        for (int i = 0; i < NWARPS / 4; ++i) {
            float4 a = p0[i];
            float4 c = p1[i];
            sum0 += (a.x + a.y) + (a.z + a.w);
            sum1 += (c.x + c.y) + (c.z + c.w);
        }
        const float rinv0 = rsqrtf(sum0 * (1.0f / D_) + EPS_);
        const float rinv1 = rsqrtf(sum1 * (1.0f / D_) + EPS_);

        const float4 xn0 = f4_scale(xc0, rinv0);
        const float4 xn1 = f4_scale(xc1, rinv1);

        if (r >= l0) {
            float4 y0, y1;
            y0.x = w0.x * h0.x + w1.x * h1.x + w2.x * h2.x + w3.x * xn0.x;
            y0.y = w0.y * h0.y + w1.y * h1.y + w2.y * h2.y + w3.y * xn0.y;
            y0.z = w0.z * h0.z + w1.z * h1.z + w2.z * h2.z + w3.z * xn0.z;
            y0.w = w0.w * h0.w + w1.w * h1.w + w2.w * h2.w + w3.w * xn0.w;

            y1.x = w0.x * h1.x + w1.x * h2.x + w2.x * xn0.x + w3.x * xn1.x;
            y1.y = w0.y * h1.y + w1.y * h2.y + w2.y * xn0.y + w3.y * xn1.y;
            y1.z = w0.z * h1.z + w1.z * h2.z + w2.z * xn0.z + w3.z * xn1.z;
            y1.w = w0.w * h1.w + w1.w * h2.w + w2.w * xn0.w + w3.w * xn1.w;

            y0.x = silu_fast(y0.x);
            y0.y = silu_fast(y0.y);
            y0.z = silu_fast(y0.z);
            y0.w = silu_fast(y0.w);
            y1.x = silu_fast(y1.x);
            y1.y = silu_fast(y1.y);
            y1.z = silu_fast(y1.z);
            y1.w = silu_fast(y1.w);

            *reinterpret_cast<float4*>(ob + (size_t)(r + 0) * D_ + d) = y0;
            *reinterpret_cast<float4*>(ob + (size_t)(r + 1) * D_ + d) = y1;
        }

        // Shift window by 2 rows.
        h0 = h2; h1 = xn0; h2 = xn1;
        xc0 = xp0; xc1 = xp1;
    }
}

extern "C" void kernel_launch(void* const* d_in, const int* in_sizes, int n_in,
                              void* d_out, int out_size)
{
    const float* x  = nullptr;
    const float* nw = nullptr;
    const float* cw = nullptr;
    for (int i = 0; i < n_in; ++i) {
        if      (in_sizes[i] == B_ * L_ * D_) x  = (const float*)d_in[i];
        else if (in_sizes[i] == D_)           nw = (const float*)d_in[i];
        else if (in_sizes[i] == K_ * D_)      cw = (const float*)d_in[i];
    }
    shortconv_kernel<<<B_ * CPB, THREADS>>>(x, nw, cw, (float*)d_out);
}

// round 6
// speedup vs baseline: 1.2857x; 1.0352x over previous
#include <cuda_runtime.h>

// ShortConv: fused RMSNorm (over D) -> depthwise causal conv1d (K=4, over L) -> SiLU
// R6: packed f32x2 math (Blackwell fma/mul/add.rn.f32x2) for the whole element-wise
//     path -> ~22% fewer issue slots in the hot loop. Data kept as ulonglong2
//     (native register pairs); scalar only at MUFU.TANH and the reductions' tails.
//     Structure identical to R3 (row pairs, 1 barrier / 2 rows, 2-row prefetch).

#define B_ 4
#define L_ 4096
#define D_ 2048
#define K_ 4

constexpr float EPS_ = 1e-5f;
constexpr int THREADS = 512;        // 512 * 4 = D
constexpr int ROWS = 32;            // L-rows per CTA (even)
constexpr int CPB = L_ / ROWS;      // CTAs per batch = 128
constexpr int NWARPS = THREADS / 32; // 16

typedef unsigned long long u64;

__device__ __forceinline__ u64 fma2(u64 a, u64 b, u64 c) {
    u64 d; asm("fma.rn.f32x2 %0, %1, %2, %3;" : "=l"(d) : "l"(a), "l"(b), "l"(c)); return d;
}
__device__ __forceinline__ u64 mul2(u64 a, u64 b) {
    u64 d; asm("mul.rn.f32x2 %0, %1, %2;" : "=l"(d) : "l"(a), "l"(b)); return d;
}
__device__ __forceinline__ u64 add2(u64 a, u64 b) {
    u64 d; asm("add.rn.f32x2 %0, %1, %2;" : "=l"(d) : "l"(a), "l"(b)); return d;
}
__device__ __forceinline__ u64 pack2(float lo, float hi) {
    u64 d; asm("mov.b64 %0, {%1, %2};" : "=l"(d) : "f"(lo), "f"(hi)); return d;
}
__device__ __forceinline__ float2 unpack2(u64 a) {
    float lo, hi; asm("mov.b64 {%0, %1}, %2;" : "=f"(lo), "=f"(hi) : "l"(a));
    return make_float2(lo, hi);
}
__device__ __forceinline__ float tanh_f(float x) {
    float t; asm("tanh.approx.f32 %0, %1;" : "=f"(t) : "f"(x)); return t;
}

// 4 floats as two packed f32x2 lanes.
struct P4 { u64 lo, hi; };

__device__ __forceinline__ P4 ld_p4(const float* p) {
    ulonglong2 v = *reinterpret_cast<const ulonglong2*>(p);
    return { v.x, v.y };
}
__device__ __forceinline__ void st_p4(float* p, P4 v) {
    *reinterpret_cast<ulonglong2*>(p) = make_ulonglong2(v.lo, v.hi);
}
// sum of squares of the 4 lanes
__device__ __forceinline__ float dotp(P4 x) {
    u64 t = mul2(x.lo, x.lo);
    t = fma2(x.hi, x.hi, t);
    float2 f = unpack2(t);
    return f.x + f.y;
}
// SiLU on 2 packed lanes: y * (0.5*tanh(0.5*y) + 0.5)
__device__ __forceinline__ u64 silu2(u64 y, u64 half2) {
    u64 yh = mul2(y, half2);
    float2 f = unpack2(yh);
    u64 t2 = pack2(tanh_f(f.x), tanh_f(f.y));
    return mul2(y, fma2(half2, t2, half2));
}

__global__ __launch_bounds__(THREADS, 2)
void shortconv_kernel(const float* __restrict__ x,
                      const float* __restrict__ norm_w,
                      const float* __restrict__ conv_w,
                      float* __restrict__ out)
{
    const int b  = blockIdx.x / CPB;
    const int l0 = (blockIdx.x % CPB) * ROWS;
    const int t  = threadIdx.x;
    const int d  = t << 2;
    const int wid = t >> 5;
    const int lane = t & 31;

    // Double-buffered warp partials: [buf][row-in-pair][warp]
    __shared__ float s_part[2][2][NWARPS];

    const u64 half2 = 0x3f0000003f000000ULL;  // {0.5f, 0.5f}

    // Fold norm_weight into conv taps (packed).
    const P4 g = ld_p4(norm_w + d);
    P4 w0 = ld_p4(conv_w + 0 * D_ + d);
    P4 w1 = ld_p4(conv_w + 1 * D_ + d);
    P4 w2 = ld_p4(conv_w + 2 * D_ + d);
    P4 w3 = ld_p4(conv_w + 3 * D_ + d);
    w0.lo = mul2(w0.lo, g.lo); w0.hi = mul2(w0.hi, g.hi);
    w1.lo = mul2(w1.lo, g.lo); w1.hi = mul2(w1.hi, g.hi);
    w2.lo = mul2(w2.lo, g.lo); w2.hi = mul2(w2.hi, g.hi);
    w3.lo = mul2(w3.lo, g.lo); w3.hi = mul2(w3.hi, g.hi);

    const float* xb = x   + (size_t)b * L_ * D_;
    float*       ob = out + (size_t)b * L_ * D_;

    // Rolling window of normalized rows.
    P4 h0 = {0ull, 0ull}, h1 = {0ull, 0ull}, h2 = {0ull, 0ull};

    const int warm = (l0 == 0) ? 0 : 4;
    const int rbeg = l0 - warm;
    const int rend = l0 + ROWS;

    P4 xc0 = ld_p4(xb + (size_t)(rbeg + 0) * D_ + d);
    P4 xc1 = ld_p4(xb + (size_t)(rbeg + 1) * D_ + d);

    int buf = 0;
    for (int r = rbeg; r < rend; r += 2, buf ^= 1) {
        // Prefetch next pair before this pair's reduction.
        P4 xp0 = {0ull, 0ull}, xp1 = {0ull, 0ull};
        if (r + 2 < rend) {
            xp0 = ld_p4(xb + (size_t)(r + 2) * D_ + d);
            xp1 = ld_p4(xb + (size_t)(r + 3) * D_ + d);
        }

        // ---- interleaved warp reductions for both rows ----
        float s0 = dotp(xc0);
        float s1 = dotp(xc1);
        #pragma unroll
        for (int o = 16; o; o >>= 1) {
            s0 += __shfl_xor_sync(0xffffffffu, s0, o);
            s1 += __shfl_xor_sync(0xffffffffu, s1, o);
        }
        if (lane == 0) {
            s_part[buf][0][wid] = s0;
            s_part[buf][1][wid] = s1;
        }
        __syncthreads();

        // Every thread sums the 16 partials (broadcast LDS.128 + packed adds).
        const ulonglong2* q0 = reinterpret_cast<const ulonglong2*>(s_part[buf][0]);
        const ulonglong2* q1 = reinterpret_cast<const ulonglong2*>(s_part[buf][1]);
        u64 a0 = 0ull, a1 = 0ull;
        #pragma unroll
        for (int i = 0; i < NWARPS / 4; ++i) {
            ulonglong2 v0 = q0[i];
            ulonglong2 v1 = q1[i];
            a0 = add2(a0, add2(v0.x, v0.y));
            a1 = add2(a1, add2(v1.x, v1.y));
        }
        float2 f0 = unpack2(a0);
        float2 f1 = unpack2(a1);
        const float rinv0 = rsqrtf((f0.x + f0.y) * (1.0f / D_) + EPS_);
        const float rinv1 = rsqrtf((f1.x + f1.y) * (1.0f / D_) + EPS_);
        const u64 rv0 = pack2(rinv0, rinv0);
        const u64 rv1 = pack2(rinv1, rinv1);

        P4 xn0 = { mul2(xc0.lo, rv0), mul2(xc0.hi, rv0) };
        P4 xn1 = { mul2(xc1.lo, rv1), mul2(xc1.hi, rv1) };

        if (r >= l0) {
            P4 y0, y1;
            y0.lo = fma2(w3.lo, xn0.lo, fma2(w2.lo, h2.lo, fma2(w1.lo, h1.lo, mul2(w0.lo, h0.lo))));
            y0.hi = fma2(w3.hi, xn0.hi, fma2(w2.hi, h2.hi, fma2(w1.hi, h1.hi, mul2(w0.hi, h0.hi))));
            y1.lo = fma2(w3.lo, xn1.lo, fma2(w2.lo, xn0.lo, fma2(w1.lo, h2.lo, mul2(w0.lo, h1.lo))));
            y1.hi = fma2(w3.hi, xn1.hi, fma2(w2.hi, xn0.hi, fma2(w1.hi, h2.hi, mul2(w0.hi, h1.hi))));

            y0.lo = silu2(y0.lo, half2);
            y0.hi = silu2(y0.hi, half2);
            y1.lo = silu2(y1.lo, half2);
            y1.hi = silu2(y1.hi, half2);

            st_p4(ob + (size_t)(r + 0) * D_ + d, y0);
            st_p4(ob + (size_t)(r + 1) * D_ + d, y1);
        }

        // Shift window by 2 rows.
        h0 = h2; h1 = xn0; h2 = xn1;
        xc0 = xp0; xc1 = xp1;
    }
}

extern "C" void kernel_launch(void* const* d_in, const int* in_sizes, int n_in,
                              void* d_out, int out_size)
{
    const float* x  = nullptr;
    const float* nw = nullptr;
    const float* cw = nullptr;
    for (int i = 0; i < n_in; ++i) {
        if      (in_sizes[i] == B_ * L_ * D_) x  = (const float*)d_in[i];
        else if (in_sizes[i] == D_)           nw = (const float*)d_in[i];
        else if (in_sizes[i] == K_ * D_)      cw = (const float*)d_in[i];
    }
    shortconv_kernel<<<B_ * CPB, THREADS>>>(x, nw, cw, (float*)d_out);
}

// round 7
// speedup vs baseline: 1.3002x; 1.0113x over previous
#include <cuda_runtime.h>

// ShortConv: fused RMSNorm (over D) -> depthwise causal conv1d (K=4, over L) -> SiLU
// R7: cp.async 4-stage smem ring for input rows. Load-to-use distance = 3 pairs
//     (~750cy) > DRAM latency, with zero register cost -> decorrelated,
//     fully-hidden global loads. Compute path identical to R6 (packed f32x2).

#define B_ 4
#define L_ 4096
#define D_ 2048
#define K_ 4

constexpr float EPS_ = 1e-5f;
constexpr int THREADS = 512;          // 512 * 4 = D
constexpr int ROWS = 32;              // L-rows per CTA (even)
constexpr int CPB = L_ / ROWS;        // 128 CTAs per batch
constexpr int NWARPS = THREADS / 32;  // 16
constexpr int NS = 4;                 // pipeline stages (row-pairs in smem)
constexpr int ROW_BYTES  = D_ * 4;        // 8192
constexpr int PAIR_BYTES = 2 * ROW_BYTES; // 16384
constexpr int SMEM_X     = NS * PAIR_BYTES;          // 65536
constexpr int SMEM_TOTAL = SMEM_X + 2 * 2 * NWARPS * 4; // + s_part 256B

typedef unsigned long long u64;

__device__ __forceinline__ u64 fma2(u64 a, u64 b, u64 c) {
    u64 d; asm("fma.rn.f32x2 %0, %1, %2, %3;" : "=l"(d) : "l"(a), "l"(b), "l"(c)); return d;
}
__device__ __forceinline__ u64 mul2(u64 a, u64 b) {
    u64 d; asm("mul.rn.f32x2 %0, %1, %2;" : "=l"(d) : "l"(a), "l"(b)); return d;
}
__device__ __forceinline__ u64 add2(u64 a, u64 b) {
    u64 d; asm("add.rn.f32x2 %0, %1, %2;" : "=l"(d) : "l"(a), "l"(b)); return d;
}
__device__ __forceinline__ u64 pack2(float lo, float hi) {
    u64 d; asm("mov.b64 %0, {%1, %2};" : "=l"(d) : "f"(lo), "f"(hi)); return d;
}
__device__ __forceinline__ float2 unpack2(u64 a) {
    float lo, hi; asm("mov.b64 {%0, %1}, %2;" : "=f"(lo), "=f"(hi) : "l"(a));
    return make_float2(lo, hi);
}
__device__ __forceinline__ float tanh_f(float x) {
    float t; asm("tanh.approx.f32 %0, %1;" : "=f"(t) : "f"(x)); return t;
}

struct P4 { u64 lo, hi; };

__device__ __forceinline__ P4 ld_p4(const float* p) {
    ulonglong2 v = *reinterpret_cast<const ulonglong2*>(p);
    return { v.x, v.y };
}
__device__ __forceinline__ void st_p4(float* p, P4 v) {
    *reinterpret_cast<ulonglong2*>(p) = make_ulonglong2(v.lo, v.hi);
}
__device__ __forceinline__ float dotp(P4 x) {
    u64 t = mul2(x.lo, x.lo);
    t = fma2(x.hi, x.hi, t);
    float2 f = unpack2(t);
    return f.x + f.y;
}
__device__ __forceinline__ u64 silu2(u64 y, u64 half2) {
    u64 yh = mul2(y, half2);
    float2 f = unpack2(yh);
    u64 t2 = pack2(tanh_f(f.x), tanh_f(f.y));
    return mul2(y, fma2(half2, t2, half2));
}
__device__ __forceinline__ void cpa16(unsigned dst, const float* src) {
    asm volatile("cp.async.cg.shared.global [%0], [%1], 16;" :: "r"(dst), "l"(src));
}

__global__ __launch_bounds__(THREADS, 2)
void shortconv_kernel(const float* __restrict__ x,
                      const float* __restrict__ norm_w,
                      const float* __restrict__ conv_w,
                      float* __restrict__ out)
{
    extern __shared__ char dynsmem[];
    float* s_part = reinterpret_cast<float*>(dynsmem + SMEM_X); // [2][2][NWARPS]
    const unsigned sx_u32 = (unsigned)__cvta_generic_to_shared(dynsmem);

    const int b  = blockIdx.x / CPB;
    const int l0 = (blockIdx.x % CPB) * ROWS;
    const int t  = threadIdx.x;
    const int d  = t << 2;
    const int wid = t >> 5;
    const int lane = t & 31;
    const unsigned toff = (unsigned)t * 16u;

    const u64 half2 = 0x3f0000003f000000ULL;  // {0.5f, 0.5f}

    // Fold norm_weight into conv taps (packed).
    const P4 g = ld_p4(norm_w + d);
    P4 w0 = ld_p4(conv_w + 0 * D_ + d);
    P4 w1 = ld_p4(conv_w + 1 * D_ + d);
    P4 w2 = ld_p4(conv_w + 2 * D_ + d);
    P4 w3 = ld_p4(conv_w + 3 * D_ + d);
    w0.lo = mul2(w0.lo, g.lo); w0.hi = mul2(w0.hi, g.hi);
    w1.lo = mul2(w1.lo, g.lo); w1.hi = mul2(w1.hi, g.hi);
    w2.lo = mul2(w2.lo, g.lo); w2.hi = mul2(w2.hi, g.hi);
    w3.lo = mul2(w3.lo, g.lo); w3.hi = mul2(w3.hi, g.hi);

    const float* xb = x   + (size_t)b * L_ * D_;
    float*       ob = out + (size_t)b * L_ * D_;

    const int warm  = (l0 == 0) ? 0 : 4;
    const int rbeg  = l0 - warm;
    const int PAIRS = (ROWS + warm) / 2;      // 16 or 18

    // ---- prologue: fill NS-1 pipeline stages ----
    #pragma unroll
    for (int p = 0; p < NS - 1; ++p) {
        const float* src = xb + (size_t)(rbeg + 2 * p) * D_ + d;
        unsigned dst = sx_u32 + (unsigned)p * PAIR_BYTES + toff;
        cpa16(dst, src);
        cpa16(dst + ROW_BYTES, src + D_);
        asm volatile("cp.async.commit_group;");
    }

    // Rolling window of normalized rows.
    P4 h0 = {0ull, 0ull}, h1 = {0ull, 0ull}, h2 = {0ull, 0ull};

    int buf = 0;
    for (int i = 0; i < PAIRS; ++i, buf ^= 1) {
        // Issue copy for stage i+NS-1 (if any), always commit to keep group math uniform.
        if (i + NS - 1 < PAIRS) {
            const int p = i + NS - 1;
            const float* src = xb + (size_t)(rbeg + 2 * p) * D_ + d;
            unsigned dst = sx_u32 + (unsigned)(p & (NS - 1)) * PAIR_BYTES + toff;
            cpa16(dst, src);
            cpa16(dst + ROW_BYTES, src + D_);
        }
        asm volatile("cp.async.commit_group;");
        asm volatile("cp.async.wait_group 3;");   // NS-1: oldest (pair i) complete

        // Read pair i from smem ring (own 16B per row -> no barrier needed).
        const char* stage = dynsmem + (size_t)(i & (NS - 1)) * PAIR_BYTES + (size_t)t * 16;
        ulonglong2 v0 = *reinterpret_cast<const ulonglong2*>(stage);
        ulonglong2 v1 = *reinterpret_cast<const ulonglong2*>(stage + ROW_BYTES);
        P4 xc0 = { v0.x, v0.y };
        P4 xc1 = { v1.x, v1.y };

        // ---- interleaved warp reductions for both rows ----
        float s0 = dotp(xc0);
        float s1 = dotp(xc1);
        #pragma unroll
        for (int o = 16; o; o >>= 1) {
            s0 += __shfl_xor_sync(0xffffffffu, s0, o);
            s1 += __shfl_xor_sync(0xffffffffu, s1, o);
        }
        if (lane == 0) {
            s_part[(buf * 2 + 0) * NWARPS + wid] = s0;
            s_part[(buf * 2 + 1) * NWARPS + wid] = s1;
        }
        __syncthreads();

        // Every thread sums the 16 partials (broadcast LDS.128 + packed adds).
        const ulonglong2* q0 = reinterpret_cast<const ulonglong2*>(s_part + (buf * 2 + 0) * NWARPS);
        const ulonglong2* q1 = reinterpret_cast<const ulonglong2*>(s_part + (buf * 2 + 1) * NWARPS);
        u64 a0 = 0ull, a1 = 0ull;
        #pragma unroll
        for (int k = 0; k < NWARPS / 4; ++k) {
            ulonglong2 u0 = q0[k];
            ulonglong2 u1 = q1[k];
            a0 = add2(a0, add2(u0.x, u0.y));
            a1 = add2(a1, add2(u1.x, u1.y));
        }
        float2 f0 = unpack2(a0);
        float2 f1 = unpack2(a1);
        const float rinv0 = rsqrtf((f0.x + f0.y) * (1.0f / D_) + EPS_);
        const float rinv1 = rsqrtf((f1.x + f1.y) * (1.0f / D_) + EPS_);
        const u64 rv0 = pack2(rinv0, rinv0);
        const u64 rv1 = pack2(rinv1, rinv1);

        P4 xn0 = { mul2(xc0.lo, rv0), mul2(xc0.hi, rv0) };
        P4 xn1 = { mul2(xc1.lo, rv1), mul2(xc1.hi, rv1) };

        const int r = rbeg + 2 * i;
        if (r >= l0) {
            P4 y0, y1;
            y0.lo = fma2(w3.lo, xn0.lo, fma2(w2.lo, h2.lo, fma2(w1.lo, h1.lo, mul2(w0.lo, h0.lo))));
            y0.hi = fma2(w3.hi, xn0.hi, fma2(w2.hi, h2.hi, fma2(w1.hi, h1.hi, mul2(w0.hi, h0.hi))));
            y1.lo = fma2(w3.lo, xn1.lo, fma2(w2.lo, xn0.lo, fma2(w1.lo, h2.lo, mul2(w0.lo, h1.lo))));
            y1.hi = fma2(w3.hi, xn1.hi, fma2(w2.hi, xn0.hi, fma2(w1.hi, h2.hi, mul2(w0.hi, h1.hi))));

            y0.lo = silu2(y0.lo, half2);
            y0.hi = silu2(y0.hi, half2);
            y1.lo = silu2(y1.lo, half2);
            y1.hi = silu2(y1.hi, half2);

            st_p4(ob + (size_t)(r + 0) * D_ + d, y0);
            st_p4(ob + (size_t)(r + 1) * D_ + d, y1);
        }

        // Shift window by 2 rows.
        h0 = h2; h1 = xn0; h2 = xn1;
    }
}

extern "C" void kernel_launch(void* const* d_in, const int* in_sizes, int n_in,
                              void* d_out, int out_size)
{
    const float* x  = nullptr;
    const float* nw = nullptr;
    const float* cw = nullptr;
    for (int i = 0; i < n_in; ++i) {
        if      (in_sizes[i] == B_ * L_ * D_) x  = (const float*)d_in[i];
        else if (in_sizes[i] == D_)           nw = (const float*)d_in[i];
        else if (in_sizes[i] == K_ * D_)      cw = (const float*)d_in[i];
    }
    // Dynamic smem > 48KB requires the opt-in attribute (host-side, idempotent,
    // not a stream op -> safe during graph capture).
    cudaFuncSetAttribute(shortconv_kernel,
                         cudaFuncAttributeMaxDynamicSharedMemorySize, SMEM_TOTAL);
    shortconv_kernel<<<B_ * CPB, THREADS, SMEM_TOTAL>>>(x, nw, cw, (float*)d_out);
}

// round 10
// speedup vs baseline: 1.3333x; 1.0255x over previous
#include <cuda_runtime.h>

// ShortConv: fused RMSNorm (over D) -> depthwise causal conv1d (K=4, over L) -> SiLU
// R8 (3rd submit; two container-acquisition infra failures, kernel never ran): MIO/LSU diet.
//  - stage-1 warp reduce: 3 shfl rounds (lanes 0-3 hold group sums) + STS x4/warp
//  - stage-2: warp0 only (LDS.128 + 3 adds + 4 shfl + rsqrt + STS rinv), 2nd barrier,
//    then ALL threads fetch rinv with a single LDS.64 (was 4x LDS.128 per thread)
//  - input path: register prefetch (R6 style), no cp.async, no ring readback
//  - compute path: packed f32x2 + tanh-SiLU (unchanged from R6)

#define B_ 4
#define L_ 4096
#define D_ 2048
#define K_ 4

constexpr float EPS_ = 1e-5f;
constexpr int THREADS = 512;          // 512 * 4 = D
constexpr int ROWS = 32;              // L-rows per CTA (even)
constexpr int CPB = L_ / ROWS;        // 128 CTAs per batch
constexpr int NWARPS = THREADS / 32;  // 16

typedef unsigned long long u64;

__device__ __forceinline__ u64 fma2(u64 a, u64 b, u64 c) {
    u64 d; asm("fma.rn.f32x2 %0, %1, %2, %3;" : "=l"(d) : "l"(a), "l"(b), "l"(c)); return d;
}
__device__ __forceinline__ u64 mul2(u64 a, u64 b) {
    u64 d; asm("mul.rn.f32x2 %0, %1, %2;" : "=l"(d) : "l"(a), "l"(b)); return d;
}
__device__ __forceinline__ u64 pack2(float lo, float hi) {
    u64 d; asm("mov.b64 %0, {%1, %2};" : "=l"(d) : "f"(lo), "f"(hi)); return d;
}
__device__ __forceinline__ float2 unpack2(u64 a) {
    float lo, hi; asm("mov.b64 {%0, %1}, %2;" : "=f"(lo), "=f"(hi) : "l"(a));
    return make_float2(lo, hi);
}
__device__ __forceinline__ float tanh_f(float x) {
    float t; asm("tanh.approx.f32 %0, %1;" : "=f"(t) : "f"(x)); return t;
}

struct P4 { u64 lo, hi; };

__device__ __forceinline__ P4 ld_p4(const float* p) {
    ulonglong2 v = *reinterpret_cast<const ulonglong2*>(p);
    return { v.x, v.y };
}
__device__ __forceinline__ void st_p4(float* p, P4 v) {
    *reinterpret_cast<ulonglong2*>(p) = make_ulonglong2(v.lo, v.hi);
}
__device__ __forceinline__ float dotp(P4 x) {
    u64 t = mul2(x.lo, x.lo);
    t = fma2(x.hi, x.hi, t);
    float2 f = unpack2(t);
    return f.x + f.y;
}
__device__ __forceinline__ u64 silu2(u64 y, u64 half2) {
    u64 yh = mul2(y, half2);
    float2 f = unpack2(yh);
    u64 t2 = pack2(tanh_f(f.x), tanh_f(f.y));
    return mul2(y, fma2(half2, t2, half2));
}

__global__ __launch_bounds__(THREADS, 2)
void shortconv_kernel(const float* __restrict__ x,
                      const float* __restrict__ norm_w,
                      const float* __restrict__ conv_w,
                      float* __restrict__ out)
{
    // Double-buffered (by iteration parity): 64 group-sums per row + rinv pair.
    __shared__ float s_part[2][2][64];
    __shared__ float s_rinv[2][2];

    const int b  = blockIdx.x / CPB;
    const int l0 = (blockIdx.x % CPB) * ROWS;
    const int t  = threadIdx.x;
    const int d  = t << 2;
    const int wid = t >> 5;
    const int lane = t & 31;

    const u64 half2 = 0x3f0000003f000000ULL;  // {0.5f, 0.5f}

    // Fold norm_weight into conv taps (packed).
    const P4 g = ld_p4(norm_w + d);
    P4 w0 = ld_p4(conv_w + 0 * D_ + d);
    P4 w1 = ld_p4(conv_w + 1 * D_ + d);
    P4 w2 = ld_p4(conv_w + 2 * D_ + d);
    P4 w3 = ld_p4(conv_w + 3 * D_ + d);
    w0.lo = mul2(w0.lo, g.lo); w0.hi = mul2(w0.hi, g.hi);
    w1.lo = mul2(w1.lo, g.lo); w1.hi = mul2(w1.hi, g.hi);
    w2.lo = mul2(w2.lo, g.lo); w2.hi = mul2(w2.hi, g.hi);
    w3.lo = mul2(w3.lo, g.lo); w3.hi = mul2(w3.hi, g.hi);

    const float* xb = x   + (size_t)b * L_ * D_;
    float*       ob = out + (size_t)b * L_ * D_;

    // Rolling window of normalized rows.
    P4 h0 = {0ull, 0ull}, h1 = {0ull, 0ull}, h2 = {0ull, 0ull};

    const int warm = (l0 == 0) ? 0 : 4;
    const int rbeg = l0 - warm;
    const int rend = l0 + ROWS;

    P4 xc0 = ld_p4(xb + (size_t)(rbeg + 0) * D_ + d);
    P4 xc1 = ld_p4(xb + (size_t)(rbeg + 1) * D_ + d);

    int buf = 0;
    for (int r = rbeg; r < rend; r += 2, buf ^= 1) {
        // Prefetch next pair before this pair's reduction.
        P4 xp0 = {0ull, 0ull}, xp1 = {0ull, 0ull};
        if (r + 2 < rend) {
            xp0 = ld_p4(xb + (size_t)(r + 2) * D_ + d);
            xp1 = ld_p4(xb + (size_t)(r + 3) * D_ + d);
        }

        // ---- stage 1: 3 shuffle rounds -> lanes 0..3 hold the 4 group sums ----
        float s0 = dotp(xc0);
        float s1 = dotp(xc1);
        #pragma unroll
        for (int o = 16; o >= 4; o >>= 1) {
            s0 += __shfl_xor_sync(0xffffffffu, s0, o);
            s1 += __shfl_xor_sync(0xffffffffu, s1, o);
        }
        if (lane < 4) {
            s_part[buf][0][(wid << 2) + lane] = s0;
            s_part[buf][1][(wid << 2) + lane] = s1;
        }
        __syncthreads();

        // ---- stage 2: warp0 reduces 64 partials per row ----
        if (wid == 0) {
            const int row = lane >> 4;                 // lanes 0-15: row0, 16-31: row1
            const float4 v = *reinterpret_cast<const float4*>(
                &s_part[buf][row][(lane & 15) << 2]);  // one LDS.128 per lane
            float s = (v.x + v.y) + (v.z + v.w);
            #pragma unroll
            for (int o = 8; o; o >>= 1)                // stays within each 16-lane half
                s += __shfl_xor_sync(0xffffffffu, s, o);
            const float rinv = rsqrtf(s * (1.0f / D_) + EPS_);
            if ((lane & 15) == 0) s_rinv[buf][row] = rinv;
        }
        __syncthreads();

        // All threads: one LDS.64 broadcast for both rinvs.
        const float2 rv = *reinterpret_cast<const float2*>(s_rinv[buf]);
        const u64 rv0 = pack2(rv.x, rv.x);
        const u64 rv1 = pack2(rv.y, rv.y);

        P4 xn0 = { mul2(xc0.lo, rv0), mul2(xc0.hi, rv0) };
        P4 xn1 = { mul2(xc1.lo, rv1), mul2(xc1.hi, rv1) };

        if (r >= l0) {
            P4 y0, y1;
            y0.lo = fma2(w3.lo, xn0.lo, fma2(w2.lo, h2.lo, fma2(w1.lo, h1.lo, mul2(w0.lo, h0.lo))));
            y0.hi = fma2(w3.hi, xn0.hi, fma2(w2.hi, h2.hi, fma2(w1.hi, h1.hi, mul2(w0.hi, h0.hi))));
            y1.lo = fma2(w3.lo, xn1.lo, fma2(w2.lo, xn0.lo, fma2(w1.lo, h2.lo, mul2(w0.lo, h1.lo))));
            y1.hi = fma2(w3.hi, xn1.hi, fma2(w2.hi, xn0.hi, fma2(w1.hi, h2.hi, mul2(w0.hi, h1.hi))));

            y0.lo = silu2(y0.lo, half2);
            y0.hi = silu2(y0.hi, half2);
            y1.lo = silu2(y1.lo, half2);
            y1.hi = silu2(y1.hi, half2);

            st_p4(ob + (size_t)(r + 0) * D_ + d, y0);
            st_p4(ob + (size_t)(r + 1) * D_ + d, y1);
        }

        // Shift window by 2 rows.
        h0 = h2; h1 = xn0; h2 = xn1;
        xc0 = xp0; xc1 = xp1;
    }
}

extern "C" void kernel_launch(void* const* d_in, const int* in_sizes, int n_in,
                              void* d_out, int out_size)
{
    const float* x  = nullptr;
    const float* nw = nullptr;
    const float* cw = nullptr;
    for (int i = 0; i < n_in; ++i) {
        if      (in_sizes[i] == B_ * L_ * D_) x  = (const float*)d_in[i];
        else if (in_sizes[i] == D_)           nw = (const float*)d_in[i];
        else if (in_sizes[i] == K_ * D_)      cw = (const float*)d_in[i];
    }
    shortconv_kernel<<<B_ * CPB, THREADS>>>(x, nw, cw, (float*)d_out);
}

// round 12
// speedup vs baseline: 1.3838x; 1.0378x over previous
#include <cuda_runtime.h>

// ShortConv: fused RMSNorm (over D) -> depthwise causal conv1d (K=4, over L) -> SiLU
// R10 (resubmit; container-acquisition infra failure, kernel never ran):
//      R7's cp.async 4-stage input ring (3-pair lookahead, zero reg cost)
//      + R8's lean reduction (3-shfl stage1, warp0-only stage2, LDS.64 broadcast).
//      MIO headroom freed by R8 now pays for the ring's LDGSTS+LDS cost.

#define B_ 4
#define L_ 4096
#define D_ 2048
#define K_ 4

constexpr float EPS_ = 1e-5f;
constexpr int THREADS = 512;          // 512 * 4 = D
constexpr int ROWS = 32;              // L-rows per CTA (even)
constexpr int CPB = L_ / ROWS;        // 128 CTAs per batch
constexpr int NWARPS = THREADS / 32;  // 16
constexpr int NS = 4;                 // ring stages (row-pairs)
constexpr int ROW_BYTES  = D_ * 4;        // 8192
constexpr int PAIR_BYTES = 2 * ROW_BYTES; // 16384
constexpr int SMEM_X     = NS * PAIR_BYTES;            // 65536
constexpr int SMEM_PART  = 2 * 2 * 64 * 4;             // 1024
constexpr int SMEM_TOTAL = SMEM_X + SMEM_PART + 16;    // + s_rinv

typedef unsigned long long u64;

__device__ __forceinline__ u64 fma2(u64 a, u64 b, u64 c) {
    u64 d; asm("fma.rn.f32x2 %0, %1, %2, %3;" : "=l"(d) : "l"(a), "l"(b), "l"(c)); return d;
}
__device__ __forceinline__ u64 mul2(u64 a, u64 b) {
    u64 d; asm("mul.rn.f32x2 %0, %1, %2;" : "=l"(d) : "l"(a), "l"(b)); return d;
}
__device__ __forceinline__ u64 pack2(float lo, float hi) {
    u64 d; asm("mov.b64 %0, {%1, %2};" : "=l"(d) : "f"(lo), "f"(hi)); return d;
}
__device__ __forceinline__ float2 unpack2(u64 a) {
    float lo, hi; asm("mov.b64 {%0, %1}, %2;" : "=f"(lo), "=f"(hi) : "l"(a));
    return make_float2(lo, hi);
}
__device__ __forceinline__ float tanh_f(float x) {
    float t; asm("tanh.approx.f32 %0, %1;" : "=f"(t) : "f"(x)); return t;
}

struct P4 { u64 lo, hi; };

__device__ __forceinline__ P4 ld_p4(const float* p) {
    ulonglong2 v = *reinterpret_cast<const ulonglong2*>(p);
    return { v.x, v.y };
}
__device__ __forceinline__ void st_p4(float* p, P4 v) {
    *reinterpret_cast<ulonglong2*>(p) = make_ulonglong2(v.lo, v.hi);
}
__device__ __forceinline__ float dotp(P4 x) {
    u64 t = mul2(x.lo, x.lo);
    t = fma2(x.hi, x.hi, t);
    float2 f = unpack2(t);
    return f.x + f.y;
}
__device__ __forceinline__ u64 silu2(u64 y, u64 half2) {
    u64 yh = mul2(y, half2);
    float2 f = unpack2(yh);
    u64 t2 = pack2(tanh_f(f.x), tanh_f(f.y));
    return mul2(y, fma2(half2, t2, half2));
}
__device__ __forceinline__ void cpa16(unsigned dst, const float* src) {
    asm volatile("cp.async.cg.shared.global [%0], [%1], 16;" :: "r"(dst), "l"(src));
}

__global__ __launch_bounds__(THREADS, 2)
void shortconv_kernel(const float* __restrict__ x,
                      const float* __restrict__ norm_w,
                      const float* __restrict__ conv_w,
                      float* __restrict__ out)
{
    extern __shared__ char dynsmem[];
    float* s_part = reinterpret_cast<float*>(dynsmem + SMEM_X);      // [2][2][64]
    float* s_rinv = reinterpret_cast<float*>(dynsmem + SMEM_X + SMEM_PART); // [2][2]
    const unsigned sx_u32 = (unsigned)__cvta_generic_to_shared(dynsmem);

    const int b  = blockIdx.x / CPB;
    const int l0 = (blockIdx.x % CPB) * ROWS;
    const int t  = threadIdx.x;
    const int d  = t << 2;
    const int wid = t >> 5;
    const int lane = t & 31;
    const unsigned toff = (unsigned)t * 16u;

    const u64 half2 = 0x3f0000003f000000ULL;  // {0.5f, 0.5f}

    // Fold norm_weight into conv taps (packed).
    const P4 g = ld_p4(norm_w + d);
    P4 w0 = ld_p4(conv_w + 0 * D_ + d);
    P4 w1 = ld_p4(conv_w + 1 * D_ + d);
    P4 w2 = ld_p4(conv_w + 2 * D_ + d);
    P4 w3 = ld_p4(conv_w + 3 * D_ + d);
    w0.lo = mul2(w0.lo, g.lo); w0.hi = mul2(w0.hi, g.hi);
    w1.lo = mul2(w1.lo, g.lo); w1.hi = mul2(w1.hi, g.hi);
    w2.lo = mul2(w2.lo, g.lo); w2.hi = mul2(w2.hi, g.hi);
    w3.lo = mul2(w3.lo, g.lo); w3.hi = mul2(w3.hi, g.hi);

    const float* xb = x   + (size_t)b * L_ * D_;
    float*       ob = out + (size_t)b * L_ * D_;

    const int warm  = (l0 == 0) ? 0 : 4;
    const int rbeg  = l0 - warm;
    const int PAIRS = (ROWS + warm) / 2;      // 16 or 18

    // ---- prologue: fill NS-1 ring stages ----
    #pragma unroll
    for (int p = 0; p < NS - 1; ++p) {
        const float* src = xb + (size_t)(rbeg + 2 * p) * D_ + d;
        unsigned dst = sx_u32 + (unsigned)p * PAIR_BYTES + toff;
        cpa16(dst, src);
        cpa16(dst + ROW_BYTES, src + D_);
        asm volatile("cp.async.commit_group;");
    }

    // Rolling window of normalized rows.
    P4 h0 = {0ull, 0ull}, h1 = {0ull, 0ull}, h2 = {0ull, 0ull};

    int buf = 0;
    for (int i = 0; i < PAIRS; ++i, buf ^= 1) {
        // Issue copy for stage i+NS-1 (if any); always commit (uniform group math).
        if (i + NS - 1 < PAIRS) {
            const int p = i + NS - 1;
            const float* src = xb + (size_t)(rbeg + 2 * p) * D_ + d;
            unsigned dst = sx_u32 + (unsigned)(p & (NS - 1)) * PAIR_BYTES + toff;
            cpa16(dst, src);
            cpa16(dst + ROW_BYTES, src + D_);
        }
        asm volatile("cp.async.commit_group;");
        asm volatile("cp.async.wait_group 3;");   // pair i complete

        // Read pair i from ring (own 16B per row -> no barrier needed).
        const char* stage = dynsmem + (size_t)(i & (NS - 1)) * PAIR_BYTES + (size_t)t * 16;
        ulonglong2 v0 = *reinterpret_cast<const ulonglong2*>(stage);
        ulonglong2 v1 = *reinterpret_cast<const ulonglong2*>(stage + ROW_BYTES);
        P4 xc0 = { v0.x, v0.y };
        P4 xc1 = { v1.x, v1.y };

        // ---- stage 1: 3 shuffle rounds -> lanes 0..3 hold the 4 group sums ----
        float s0 = dotp(xc0);
        float s1 = dotp(xc1);
        #pragma unroll
        for (int o = 16; o >= 4; o >>= 1) {
            s0 += __shfl_xor_sync(0xffffffffu, s0, o);
            s1 += __shfl_xor_sync(0xffffffffu, s1, o);
        }
        if (lane < 4) {
            s_part[(buf * 2 + 0) * 64 + (wid << 2) + lane] = s0;
            s_part[(buf * 2 + 1) * 64 + (wid << 2) + lane] = s1;
        }
        __syncthreads();

        // ---- stage 2: warp0 reduces 64 partials per row ----
        if (wid == 0) {
            const int row = lane >> 4;                 // lanes 0-15: row0, 16-31: row1
            const float4 v = *reinterpret_cast<const float4*>(
                &s_part[(buf * 2 + row) * 64 + ((lane & 15) << 2)]);
            float s = (v.x + v.y) + (v.z + v.w);
            #pragma unroll
            for (int o = 8; o; o >>= 1)                // stays within each 16-lane half
                s += __shfl_xor_sync(0xffffffffu, s, o);
            const float rinv = rsqrtf(s * (1.0f / D_) + EPS_);
            if ((lane & 15) == 0) s_rinv[buf * 2 + row] = rinv;
        }
        __syncthreads();

        // All threads: one LDS.64 broadcast for both rinvs.
        const float2 rv = *reinterpret_cast<const float2*>(&s_rinv[buf * 2]);
        const u64 rv0 = pack2(rv.x, rv.x);
        const u64 rv1 = pack2(rv.y, rv.y);

        P4 xn0 = { mul2(xc0.lo, rv0), mul2(xc0.hi, rv0) };
        P4 xn1 = { mul2(xc1.lo, rv1), mul2(xc1.hi, rv1) };

        const int r = rbeg + 2 * i;
        if (r >= l0) {
            P4 y0, y1;
            y0.lo = fma2(w3.lo, xn0.lo, fma2(w2.lo, h2.lo, fma2(w1.lo, h1.lo, mul2(w0.lo, h0.lo))));
            y0.hi = fma2(w3.hi, xn0.hi, fma2(w2.hi, h2.hi, fma2(w1.hi, h1.hi, mul2(w0.hi, h0.hi))));
            y1.lo = fma2(w3.lo, xn1.lo, fma2(w2.lo, xn0.lo, fma2(w1.lo, h2.lo, mul2(w0.lo, h1.lo))));
            y1.hi = fma2(w3.hi, xn1.hi, fma2(w2.hi, xn0.hi, fma2(w1.hi, h2.hi, mul2(w0.hi, h1.hi))));

            y0.lo = silu2(y0.lo, half2);
            y0.hi = silu2(y0.hi, half2);
            y1.lo = silu2(y1.lo, half2);
            y1.hi = silu2(y1.hi, half2);

            st_p4(ob + (size_t)(r + 0) * D_ + d, y0);
            st_p4(ob + (size_t)(r + 1) * D_ + d, y1);
        }

        // Shift window by 2 rows.
        h0 = h2; h1 = xn0; h2 = xn1;
    }
}

extern "C" void kernel_launch(void* const* d_in, const int* in_sizes, int n_in,
                              void* d_out, int out_size)
{
    const float* x  = nullptr;
    const float* nw = nullptr;
    const float* cw = nullptr;
    for (int i = 0; i < n_in; ++i) {
        if      (in_sizes[i] == B_ * L_ * D_) x  = (const float*)d_in[i];
        else if (in_sizes[i] == D_)           nw = (const float*)d_in[i];
        else if (in_sizes[i] == K_ * D_)      cw = (const float*)d_in[i];
    }
    // >48KB dynamic smem opt-in (host attribute set, not a stream op; capture-safe).
    cudaFuncSetAttribute(shortconv_kernel,
                         cudaFuncAttributeMaxDynamicSharedMemorySize, SMEM_TOTAL);
    shortconv_kernel<<<B_ * CPB, THREADS, SMEM_TOTAL>>>(x, nw, cw, (float*)d_out);
}

// round 13
// speedup vs baseline: 1.4391x; 1.0400x over previous
#include <cuda_runtime.h>

// ShortConv: fused RMSNorm (over D) -> depthwise causal conv1d (K=4, over L) -> SiLU
// R12: QUAD phases — 4 rows per barrier phase.
//  - reduce phase: 4 independent dot+3-shfl chains (4-way ILP), 1 barrier
//  - stage 2: warps 0..3 each reduce one row (16 lanes x LDS.128 + 4 shfl), 1 barrier
//  - compute phase: normalize+conv+SiLU+store 4 rows back-to-back
//  - cp.async ring at quad granularity (2 stages x 32KB, 1-quad lookahead)
//  Halved barrier count/row, 4x-amortized stage-2 chain vs R10.

#define B_ 4
#define L_ 4096
#define D_ 2048
#define K_ 4

constexpr float EPS_ = 1e-5f;
constexpr int THREADS = 512;          // 512 * 4 = D
constexpr int ROWS = 32;              // L-rows per CTA
constexpr int CPB = L_ / ROWS;        // 128 CTAs per batch
constexpr int QUAD = 4;               // rows per phase
constexpr int ROW_BYTES  = D_ * 4;            // 8192
constexpr int QUAD_BYTES = QUAD * ROW_BYTES;  // 32768
constexpr int NSQ = 2;                // ring stages (quads)
constexpr int SMEM_X    = NSQ * QUAD_BYTES;   // 65536
constexpr int SMEM_PART = 2 * 4 * 64 * 4;     // [buf][row][64] = 2048
constexpr int SMEM_TOTAL = SMEM_X + SMEM_PART + 2 * 4 * 4; // + rinv[2][4]

typedef unsigned long long u64;

__device__ __forceinline__ u64 fma2(u64 a, u64 b, u64 c) {
    u64 d; asm("fma.rn.f32x2 %0, %1, %2, %3;" : "=l"(d) : "l"(a), "l"(b), "l"(c)); return d;
}
__device__ __forceinline__ u64 mul2(u64 a, u64 b) {
    u64 d; asm("mul.rn.f32x2 %0, %1, %2;" : "=l"(d) : "l"(a), "l"(b)); return d;
}
__device__ __forceinline__ u64 pack2(float lo, float hi) {
    u64 d; asm("mov.b64 %0, {%1, %2};" : "=l"(d) : "f"(lo), "f"(hi)); return d;
}
__device__ __forceinline__ float2 unpack2(u64 a) {
    float lo, hi; asm("mov.b64 {%0, %1}, %2;" : "=f"(lo), "=f"(hi) : "l"(a));
    return make_float2(lo, hi);
}
__device__ __forceinline__ float tanh_f(float x) {
    float t; asm("tanh.approx.f32 %0, %1;" : "=f"(t) : "f"(x)); return t;
}

struct P4 { u64 lo, hi; };

__device__ __forceinline__ P4 ld_p4(const float* p) {
    ulonglong2 v = *reinterpret_cast<const ulonglong2*>(p);
    return { v.x, v.y };
}
__device__ __forceinline__ void st_p4(float* p, P4 v) {
    *reinterpret_cast<ulonglong2*>(p) = make_ulonglong2(v.lo, v.hi);
}
__device__ __forceinline__ float dotp(P4 x) {
    u64 t = mul2(x.lo, x.lo);
    t = fma2(x.hi, x.hi, t);
    float2 f = unpack2(t);
    return f.x + f.y;
}
__device__ __forceinline__ u64 silu2(u64 y, u64 half2) {
    u64 yh = mul2(y, half2);
    float2 f = unpack2(yh);
    u64 t2 = pack2(tanh_f(f.x), tanh_f(f.y));
    return mul2(y, fma2(half2, t2, half2));
}
__device__ __forceinline__ void cpa16(unsigned dst, const float* src) {
    asm volatile("cp.async.cg.shared.global [%0], [%1], 16;" :: "r"(dst), "l"(src));
}
__device__ __forceinline__ P4 norm4(P4 x, u64 rv) {
    return { mul2(x.lo, rv), mul2(x.hi, rv) };
}

__global__ __launch_bounds__(THREADS, 2)
void shortconv_kernel(const float* __restrict__ x,
                      const float* __restrict__ norm_w,
                      const float* __restrict__ conv_w,
                      float* __restrict__ out)
{
    extern __shared__ char dynsmem[];
    float* s_part = reinterpret_cast<float*>(dynsmem + SMEM_X);             // [2][4][64]
    float* s_rinv = reinterpret_cast<float*>(dynsmem + SMEM_X + SMEM_PART); // [2][4]
    const unsigned sx_u32 = (unsigned)__cvta_generic_to_shared(dynsmem);

    const int b  = blockIdx.x / CPB;
    const int l0 = (blockIdx.x % CPB) * ROWS;
    const int t  = threadIdx.x;
    const int d  = t << 2;
    const int wid = t >> 5;
    const int lane = t & 31;
    const unsigned toff = (unsigned)t * 16u;

    const u64 half2 = 0x3f0000003f000000ULL;  // {0.5f, 0.5f}

    // Fold norm_weight into conv taps (packed).
    const P4 g = ld_p4(norm_w + d);
    P4 w0 = ld_p4(conv_w + 0 * D_ + d);
    P4 w1 = ld_p4(conv_w + 1 * D_ + d);
    P4 w2 = ld_p4(conv_w + 2 * D_ + d);
    P4 w3 = ld_p4(conv_w + 3 * D_ + d);
    w0.lo = mul2(w0.lo, g.lo); w0.hi = mul2(w0.hi, g.hi);
    w1.lo = mul2(w1.lo, g.lo); w1.hi = mul2(w1.hi, g.hi);
    w2.lo = mul2(w2.lo, g.lo); w2.hi = mul2(w2.hi, g.hi);
    w3.lo = mul2(w3.lo, g.lo); w3.hi = mul2(w3.hi, g.hi);

    const float* xb = x   + (size_t)b * L_ * D_;
    float*       ob = out + (size_t)b * L_ * D_;

    const int warm  = (l0 == 0) ? 0 : QUAD;   // halo = exactly one quad
    const int rbeg  = l0 - warm;
    const int QUADS = (ROWS + warm) / QUAD;   // 8 or 9

    // ---- prologue: fill ring stage 0 with quad 0 ----
    {
        const float* src = xb + (size_t)rbeg * D_ + d;
        unsigned dst = sx_u32 + toff;
        #pragma unroll
        for (int j = 0; j < QUAD; ++j)
            cpa16(dst + (unsigned)j * ROW_BYTES, src + (size_t)j * D_);
        asm volatile("cp.async.commit_group;");
    }

    // Rolling window of normalized rows.
    P4 h0 = {0ull, 0ull}, h1 = {0ull, 0ull}, h2 = {0ull, 0ull};

    int buf = 0;
    for (int i = 0; i < QUADS; ++i, buf ^= 1) {
        // Issue quad i+1 (if any); always commit (uniform group accounting).
        if (i + 1 < QUADS) {
            const float* src = xb + (size_t)(rbeg + (i + 1) * QUAD) * D_ + d;
            unsigned dst = sx_u32 + (unsigned)((i + 1) & (NSQ - 1)) * QUAD_BYTES + toff;
            #pragma unroll
            for (int j = 0; j < QUAD; ++j)
                cpa16(dst + (unsigned)j * ROW_BYTES, src + (size_t)j * D_);
        }
        asm volatile("cp.async.commit_group;");
        asm volatile("cp.async.wait_group 1;");   // quad i complete

        // Read quad i from ring (own 16B per row -> no barrier needed).
        const char* stage = dynsmem + (size_t)(i & (NSQ - 1)) * QUAD_BYTES + (size_t)t * 16;
        ulonglong2 v0 = *reinterpret_cast<const ulonglong2*>(stage);
        ulonglong2 v1 = *reinterpret_cast<const ulonglong2*>(stage + ROW_BYTES);
        ulonglong2 v2 = *reinterpret_cast<const ulonglong2*>(stage + 2 * ROW_BYTES);
        ulonglong2 v3 = *reinterpret_cast<const ulonglong2*>(stage + 3 * ROW_BYTES);
        P4 xc0 = { v0.x, v0.y }, xc1 = { v1.x, v1.y };
        P4 xc2 = { v2.x, v2.y }, xc3 = { v3.x, v3.y };

        // ---- stage 1: 4 interleaved 3-round shfl chains -> lanes 0..3 ----
        float s0 = dotp(xc0), s1 = dotp(xc1), s2 = dotp(xc2), s3 = dotp(xc3);
        #pragma unroll
        for (int o = 16; o >= 4; o >>= 1) {
            s0 += __shfl_xor_sync(0xffffffffu, s0, o);
            s1 += __shfl_xor_sync(0xffffffffu, s1, o);
            s2 += __shfl_xor_sync(0xffffffffu, s2, o);
            s3 += __shfl_xor_sync(0xffffffffu, s3, o);
        }
        if (lane < 4) {
            const int idx = (wid << 2) + lane;
            s_part[(buf * 4 + 0) * 64 + idx] = s0;
            s_part[(buf * 4 + 1) * 64 + idx] = s1;
            s_part[(buf * 4 + 2) * 64 + idx] = s2;
            s_part[(buf * 4 + 3) * 64 + idx] = s3;
        }
        __syncthreads();

        // ---- stage 2: warps 0..3 each reduce one row's 64 partials ----
        if (wid < 4 && lane < 16) {
            const float4 v = *reinterpret_cast<const float4*>(
                &s_part[(buf * 4 + wid) * 64 + (lane << 2)]);
            float s = (v.x + v.y) + (v.z + v.w);
            #pragma unroll
            for (int o = 8; o; o >>= 1)
                s += __shfl_xor_sync(0x0000ffffu, s, o);
            if (lane == 0)
                s_rinv[buf * 4 + wid] = rsqrtf(s * (1.0f / D_) + EPS_);
        }
        __syncthreads();

        // All threads: one LDS.128 broadcast for the 4 rinvs.
        const float4 rq = *reinterpret_cast<const float4*>(&s_rinv[buf * 4]);

        P4 xn0 = norm4(xc0, pack2(rq.x, rq.x));
        P4 xn1 = norm4(xc1, pack2(rq.y, rq.y));
        P4 xn2 = norm4(xc2, pack2(rq.z, rq.z));
        P4 xn3 = norm4(xc3, pack2(rq.w, rq.w));

        if (i > 0 || warm == 0) {   // warm quad (i==0 when warm) produces no output
            const int r = rbeg + i * QUAD;
            P4 y0, y1, y2, y3;
            y0.lo = fma2(w3.lo, xn0.lo, fma2(w2.lo, h2.lo,  fma2(w1.lo, h1.lo,  mul2(w0.lo, h0.lo))));
            y0.hi = fma2(w3.hi, xn0.hi, fma2(w2.hi, h2.hi,  fma2(w1.hi, h1.hi,  mul2(w0.hi, h0.hi))));
            y1.lo = fma2(w3.lo, xn1.lo, fma2(w2.lo, xn0.lo, fma2(w1.lo, h2.lo,  mul2(w0.lo, h1.lo))));
            y1.hi = fma2(w3.hi, xn1.hi, fma2(w2.hi, xn0.hi, fma2(w1.hi, h2.hi,  mul2(w0.hi, h1.hi))));
            y2.lo = fma2(w3.lo, xn2.lo, fma2(w2.lo, xn1.lo, fma2(w1.lo, xn0.lo, mul2(w0.lo, h2.lo))));
            y2.hi = fma2(w3.hi, xn2.hi, fma2(w2.hi, xn1.hi, fma2(w1.hi, xn0.hi, mul2(w0.hi, h2.hi))));
            y3.lo = fma2(w3.lo, xn3.lo, fma2(w2.lo, xn2.lo, fma2(w1.lo, xn1.lo, mul2(w0.lo, xn0.lo))));
            y3.hi = fma2(w3.hi, xn3.hi, fma2(w2.hi, xn2.hi, fma2(w1.hi, xn1.hi, mul2(w0.hi, xn0.hi))));

            y0.lo = silu2(y0.lo, half2); y0.hi = silu2(y0.hi, half2);
            y1.lo = silu2(y1.lo, half2); y1.hi = silu2(y1.hi, half2);
            y2.lo = silu2(y2.lo, half2); y2.hi = silu2(y2.hi, half2);
            y3.lo = silu2(y3.lo, half2); y3.hi = silu2(y3.hi, half2);

            st_p4(ob + (size_t)(r + 0) * D_ + d, y0);
            st_p4(ob + (size_t)(r + 1) * D_ + d, y1);
            st_p4(ob + (size_t)(r + 2) * D_ + d, y2);
            st_p4(ob + (size_t)(r + 3) * D_ + d, y3);
        }

        // Shift window: last 3 normalized rows of this quad.
        h0 = xn1; h1 = xn2; h2 = xn3;
    }
}

extern "C" void kernel_launch(void* const* d_in, const int* in_sizes, int n_in,
                              void* d_out, int out_size)
{
    const float* x  = nullptr;
    const float* nw = nullptr;
    const float* cw = nullptr;
    for (int i = 0; i < n_in; ++i) {
        if      (in_sizes[i] == B_ * L_ * D_) x  = (const float*)d_in[i];
        else if (in_sizes[i] == D_)           nw = (const float*)d_in[i];
        else if (in_sizes[i] == K_ * D_)      cw = (const float*)d_in[i];
    }
    // >48KB dynamic smem opt-in (host attribute, capture-safe).
    cudaFuncSetAttribute(shortconv_kernel,
                         cudaFuncAttributeMaxDynamicSharedMemorySize, SMEM_TOTAL);
    shortconv_kernel<<<B_ * CPB, THREADS, SMEM_TOTAL>>>(x, nw, cw, (float*)d_out);
}